// round 3
// baseline (speedup 1.0000x reference)
#include <cuda_runtime.h>
#include <cuda_bf16.h>
#include <math.h>

#define NN      3072          // nodes
#define INDIM   512
#define HD      512           // H*D
#define QKVW    1536          // q|k|v concat width
#define MW      96            // mask words per row (3072/32)
#define H7Q     448           // col offset of head-7 (7*64)
#define NPART   24            // colsum row-chunks (3072/128)
#define APAD    132           // padded A-tile row stride (bank-conflict-free, 16B-aligned)

// ---- scratch (device globals: no allocation allowed) ----
__device__ float    g_QKV[NN * QKVW];        // [n][0:512)=Q, [512:1024)=K, [1024:1536)=V
__device__ unsigned g_mask[NN * MW];         // dedup adjacency bitmask, row=src, bit=dst
__device__ float    g_part[NPART * HD];      // colsum partials
__device__ float    g_sumV[HD];              // column sums of V
__device__ int      g_is64;                  // edge_index dtype flag

// ---------------------------------------------------------------------------
// 0) zero the bitmask (graph replays re-run everything; must be idempotent)
// ---------------------------------------------------------------------------
__global__ void zero_mask_kernel() {
    int i = blockIdx.x * blockDim.x + threadIdx.x;
    int stride = gridDim.x * blockDim.x;
    for (; i < NN * MW; i += stride) g_mask[i] = 0u;
}

// ---------------------------------------------------------------------------
// 1) detect int64 vs int32 edge_index. If int64 (values < 3072 => high half
//    zero), every odd int32 word of the first 2*nscan words is zero.
// ---------------------------------------------------------------------------
__global__ void detect_kernel(const int* __restrict__ p, int nscan) {
    __shared__ int s_nz;
    if (threadIdx.x == 0) s_nz = 0;
    __syncthreads();
    int nz = 0;
    for (int i = threadIdx.x; i < nscan; i += blockDim.x)
        if (p[2 * i + 1] != 0) nz = 1;
    if (nz) atomicOr(&s_nz, 1);
    __syncthreads();
    if (threadIdx.x == 0) g_is64 = s_nz ? 0 : 1;
}

// ---------------------------------------------------------------------------
// 2) build dedup bitmask: bit(src, dst). atomicOr is idempotent -> dedup.
// ---------------------------------------------------------------------------
__global__ void build_mask_kernel(const void* __restrict__ ei, int E) {
    int e = blockIdx.x * blockDim.x + threadIdx.x;
    if (e >= E) return;
    int src, dst;
    if (g_is64) {
        const long long* p = (const long long*)ei;
        src = (int)p[e];
        dst = (int)p[E + e];
    } else {
        const int* p = (const int*)ei;
        src = p[e];
        dst = p[E + e];
    }
    if ((unsigned)src < (unsigned)NN && (unsigned)dst < (unsigned)NN)
        atomicOr(&g_mask[src * MW + (dst >> 5)], 1u << (dst & 31));
}

// ---------------------------------------------------------------------------
// 3) fused projection GEMM: QKV = x @ [Wq|Wk|Wv] + [bq|bk|bv]
//    C is [3072 x 1536], K=512. 128x128 tile, BK=16, double-buffered smem,
//    256 threads, 8x8 microtile, one __syncthreads per k-iteration.
// ---------------------------------------------------------------------------
__global__ __launch_bounds__(256, 2) void proj_gemm_kernel(
    const float* __restrict__ x,
    const float* __restrict__ Wq, const float* __restrict__ Wk, const float* __restrict__ Wv,
    const float* __restrict__ bq, const float* __restrict__ bk, const float* __restrict__ bv)
{
    __shared__ float As[2][16][APAD];   // As[buf][k][m] (x transposed in tile, padded)
    __shared__ float Bs[2][16][128];    // Bs[buf][k][n]

    const int tid = threadIdx.x;
    const int rowBase = blockIdx.y * 128;
    const int colBase = blockIdx.x * 128;

    // which weight matrix does this 128-col block live in? (512 % 128 == 0)
    const int wsel = colBase >> 9;               // /512
    const float* W = (wsel == 0) ? Wq : (wsel == 1) ? Wk : Wv;
    const float* B = (wsel == 0) ? bq : (wsel == 1) ? bk : bv;
    const int jloc = colBase - (wsel << 9);

    // ---- load index precompute ----
    // A tile: 128 rows x 16 k -> 2048 floats, 256 thr x 2 float4 along k.
    const int ar  = tid >> 1;              // 0..127  row in tile
    const int ak8 = (tid & 1) << 3;        // 0 or 8  (two float4: ak8, ak8+4)
    // B tile: 16 k x 128 cols -> 2048 floats, 256 thr x 2 float4 along j.
    const int bk_ = tid >> 5;              // 0..7    (k rows bk_, bk_+8)
    const int bj  = (tid & 31) << 2;       // 0..124

    // ---- compute index ----
    const int ty = tid >> 4;               // 0..15 -> 8 rows
    const int tx = tid & 15;               // 0..15 -> 8 cols

    const float* aPtr = x + (rowBase + ar) * INDIM + ak8;
    const float* bPtr = W + bk_ * HD + jloc + bj;

    float acc[8][8];
#pragma unroll
    for (int i = 0; i < 8; i++)
#pragma unroll
        for (int j = 0; j < 8; j++) acc[i][j] = 0.f;

    // ---- prologue: tile 0 -> buffer 0 ----
    {
        float4 a0 = *(const float4*)(aPtr);
        float4 a1 = *(const float4*)(aPtr + 4);
        float4 b0 = *(const float4*)(bPtr);
        float4 b1 = *(const float4*)(bPtr + 8 * HD);
        As[0][ak8 + 0][ar] = a0.x;  As[0][ak8 + 1][ar] = a0.y;
        As[0][ak8 + 2][ar] = a0.z;  As[0][ak8 + 3][ar] = a0.w;
        As[0][ak8 + 4][ar] = a1.x;  As[0][ak8 + 5][ar] = a1.y;
        As[0][ak8 + 6][ar] = a1.z;  As[0][ak8 + 7][ar] = a1.w;
        *(float4*)(&Bs[0][bk_][bj])     = b0;
        *(float4*)(&Bs[0][bk_ + 8][bj]) = b1;
    }
    __syncthreads();

    const int NIT = INDIM / 16;            // 32
    for (int it = 0; it < NIT; it++) {
        const int buf = it & 1;
        float4 a0, a1, b0, b1;
        if (it + 1 < NIT) {
            const float* ap = aPtr + (it + 1) * 16;
            const float* bp = bPtr + (it + 1) * 16 * HD;
            a0 = *(const float4*)(ap);
            a1 = *(const float4*)(ap + 4);
            b0 = *(const float4*)(bp);
            b1 = *(const float4*)(bp + 8 * HD);
        }

#pragma unroll
        for (int kk = 0; kk < 16; kk++) {
            float a[8], b[8];
            *(float4*)(a)     = *(const float4*)(&As[buf][kk][ty * 8]);
            *(float4*)(a + 4) = *(const float4*)(&As[buf][kk][ty * 8 + 4]);
            *(float4*)(b)     = *(const float4*)(&Bs[buf][kk][tx * 8]);
            *(float4*)(b + 4) = *(const float4*)(&Bs[buf][kk][tx * 8 + 4]);
#pragma unroll
            for (int i = 0; i < 8; i++)
#pragma unroll
                for (int j = 0; j < 8; j++) acc[i][j] = fmaf(a[i], b[j], acc[i][j]);
        }

        if (it + 1 < NIT) {
            const int nb = buf ^ 1;
            As[nb][ak8 + 0][ar] = a0.x;  As[nb][ak8 + 1][ar] = a0.y;
            As[nb][ak8 + 2][ar] = a0.z;  As[nb][ak8 + 3][ar] = a0.w;
            As[nb][ak8 + 4][ar] = a1.x;  As[nb][ak8 + 5][ar] = a1.y;
            As[nb][ak8 + 6][ar] = a1.z;  As[nb][ak8 + 7][ar] = a1.w;
            *(float4*)(&Bs[nb][bk_][bj])     = b0;
            *(float4*)(&Bs[nb][bk_ + 8][bj]) = b1;
            __syncthreads();
        }
    }

#pragma unroll
    for (int i = 0; i < 8; i++) {
        const int r = rowBase + ty * 8 + i;
        float* orow = g_QKV + r * QKVW + colBase;
#pragma unroll
        for (int j = 0; j < 8; j += 4) {
            const int cl = tx * 8 + j;
            float4 o;
            o.x = acc[i][j + 0] + B[jloc + cl + 0];
            o.y = acc[i][j + 1] + B[jloc + cl + 1];
            o.z = acc[i][j + 2] + B[jloc + cl + 2];
            o.w = acc[i][j + 3] + B[jloc + cl + 3];
            *(float4*)(orow + cl) = o;
        }
    }
}

// ---------------------------------------------------------------------------
// 4a) column partial sums of V (coalesced): block(y)=row chunk of 128,
//     block(x)=col chunk of 128. Deterministic (no float atomics).
// ---------------------------------------------------------------------------
__global__ void colsum_partial_kernel() {
    const int col = blockIdx.x * 128 + threadIdx.x;     // 0..511
    const int n0  = blockIdx.y * 128;
    float s = 0.f;
    const float* base = g_QKV + 1024 + col;
#pragma unroll 4
    for (int i = 0; i < 128; i++)
        s += base[(n0 + i) * QKVW];
    g_part[blockIdx.y * HD + col] = s;
}

// 4b) reduce partials -> g_sumV
__global__ void colsum_reduce_kernel() {
    const int col = blockIdx.x * 128 + threadIdx.x;
    float s = 0.f;
#pragma unroll
    for (int p = 0; p < NPART; p++)
        s += g_part[p * HD + col];
    g_sumV[col] = s;
}

// ---------------------------------------------------------------------------
// 5) heads 0..6: uniform softmax -> out[n][c] = sumV[c] / N   (c < 448)
// ---------------------------------------------------------------------------
__global__ void fill_kernel(float* __restrict__ out) {
    int i = blockIdx.x * blockDim.x + threadIdx.x;
    int stride = gridDim.x * blockDim.x;
    const float invN = 1.0f / (float)NN;
    for (; i < NN * H7Q; i += stride) {
        int n = i / H7Q;
        int c = i - n * H7Q;
        out[n * HD + c] = g_sumV[c] * invN;
    }
}

// ---------------------------------------------------------------------------
// 6) head 7: sparse-corrected uniform softmax.
//    out7[n,d] = (sumV7[d] + sum_{m in E(n)} (e^s - 1) v7[m,d])
//              / (N + sum (e^s - 1)),   s = q7[n].k7[m] / 8
//    one warp per row n; lane handles d and d+32.
// ---------------------------------------------------------------------------
__global__ __launch_bounds__(32) void head7_kernel(float* __restrict__ out) {
    const int n = blockIdx.x;
    const int lane = threadIdx.x;

    const float* qrow = g_QKV + n * QKVW + H7Q;          // head-7 Q
    const float qa = qrow[lane];
    const float qb = qrow[lane + 32];

    float acc0 = 0.f, acc1 = 0.f, wsum = 0.f;
    const unsigned* mrow = g_mask + n * MW;

    for (int w = 0; w < MW; w++) {
        unsigned bits = mrow[w];
        while (bits) {
            int b = __ffs(bits) - 1;
            bits &= bits - 1;
            int m = (w << 5) + b;
            const float* krow = g_QKV + m * QKVW + 512 + H7Q;   // head-7 K
            float p = qa * krow[lane] + qb * krow[lane + 32];
#pragma unroll
            for (int off = 16; off; off >>= 1)
                p += __shfl_xor_sync(0xffffffffu, p, off);
            float s = p * 0.125f;                                // 1/sqrt(64)
            float wgt = __expf(s) - 1.f;
            const float* vrow = g_QKV + m * QKVW + 1024 + H7Q;   // head-7 V
            acc0 += wgt * vrow[lane];
            acc1 += wgt * vrow[lane + 32];
            wsum += wgt;
        }
    }

    float denom = (float)NN + wsum;
    out[n * HD + H7Q + lane]      = (g_sumV[H7Q + lane]      + acc0) / denom;
    out[n * HD + H7Q + lane + 32] = (g_sumV[H7Q + lane + 32] + acc1) / denom;
}

// ---------------------------------------------------------------------------
extern "C" void kernel_launch(void* const* d_in, const int* in_sizes, int n_in,
                              void* d_out, int out_size) {
    const float* x  = (const float*)d_in[0];
    const void*  ei = d_in[1];
    const float* Wq = (const float*)d_in[2];
    const float* Wk = (const float*)d_in[3];
    const float* Wv = (const float*)d_in[4];
    const float* bq = (const float*)d_in[5];
    const float* bk = (const float*)d_in[6];
    const float* bv = (const float*)d_in[7];
    float* out = (float*)d_out;

    const int E = in_sizes[1] / 2;

    zero_mask_kernel<<<576, 256>>>();
    int nscan = E < 2048 ? E : 2048;
    detect_kernel<<<1, 256>>>((const int*)ei, nscan);
    build_mask_kernel<<<(E + 255) / 256, 256>>>(ei, E);

    proj_gemm_kernel<<<dim3(QKVW / 128, NN / 128), 256>>>(x, Wq, Wk, Wv, bq, bk, bv);

    colsum_partial_kernel<<<dim3(HD / 128, NPART), 128>>>();
    colsum_reduce_kernel<<<HD / 128, 128>>>();
    fill_kernel<<<(NN * H7Q + 255) / 256, 256>>>(out);
    head7_kernel<<<NN, 32>>>(out);
}

// round 12
// speedup vs baseline: 2.2108x; 2.2108x over previous
#include <cuda_runtime.h>
#include <cuda_bf16.h>
#include <math.h>
#include <stdint.h>

#define NN      3072          // nodes
#define INDIM   512
#define HD      512           // H*D
#define MW      96            // mask words per row (3072/32)
#define H7Q     448           // col offset of head-7 (7*64)
#define P7W     192           // q7|k7|v7 compact row width
#define NPARTX  24            // x-rowsum chunks (3072/128)

// GEMM tiling (head-7 projection: [3072 x 192], K=512, split in 2 K-halves)
#define GTM     64
#define GBK     16
#define KHALF   256
#define SPAD    68            // padded smem row (floats), 16B-aligned, bank-safe

// ---- scratch (device globals: no allocation allowed) ----
__device__ unsigned g_mask[NN * MW];        // dedup adjacency bitmask
__device__ float    g_xpart[NPARTX * INDIM];// x row-sum partials
__device__ float    g_sumV[HD];             // column sums of V (all 512)
__device__ float    g_p7[2][NN * P7W];      // K-split GEMM partials
__device__ float    g_qkv7[NN * P7W];       // [n][0:64)=q7 [64:128)=k7 [128:192)=v7
__device__ int      g_is64;                 // edge_index dtype flag

// ---------------------------------------------------------------------------
// 0) zero the bitmask (graph replays must be idempotent)
// ---------------------------------------------------------------------------
__global__ void zero_mask_kernel() {
    int i = blockIdx.x * blockDim.x + threadIdx.x;
    int stride = gridDim.x * blockDim.x;
    for (; i < NN * MW; i += stride) g_mask[i] = 0u;
}

// ---------------------------------------------------------------------------
// 1) detect int64 vs int32 edge_index (values < 3072 => int64 high words zero)
// ---------------------------------------------------------------------------
__global__ void detect_kernel(const int* __restrict__ p, int nscan) {
    __shared__ int s_nz;
    if (threadIdx.x == 0) s_nz = 0;
    __syncthreads();
    int nz = 0;
    for (int i = threadIdx.x; i < nscan; i += blockDim.x)
        if (p[2 * i + 1] != 0) nz = 1;
    if (nz) atomicOr(&s_nz, 1);
    __syncthreads();
    if (threadIdx.x == 0) g_is64 = s_nz ? 0 : 1;
}

// ---------------------------------------------------------------------------
// 2) build dedup bitmask: bit(src, dst). atomicOr is idempotent -> dedup.
// ---------------------------------------------------------------------------
__global__ void build_mask_kernel(const void* __restrict__ ei, int E) {
    int e = blockIdx.x * blockDim.x + threadIdx.x;
    if (e >= E) return;
    int src, dst;
    if (g_is64) {
        const long long* p = (const long long*)ei;
        src = (int)p[e]; dst = (int)p[E + e];
    } else {
        const int* p = (const int*)ei;
        src = p[e]; dst = p[E + e];
    }
    if ((unsigned)src < (unsigned)NN && (unsigned)dst < (unsigned)NN)
        atomicOr(&g_mask[src * MW + (dst >> 5)], 1u << (dst & 31));
}

// ---------------------------------------------------------------------------
// 3a) x row-sum partials: g_xpart[by][col] = sum over 128 rows of x[:,col]
// ---------------------------------------------------------------------------
__global__ void xsum_partial_kernel(const float* __restrict__ x) {
    const int col = blockIdx.x * 128 + threadIdx.x;     // 0..511
    const int n0  = blockIdx.y * 128;
    float s = 0.f;
    const float* base = x + col;
#pragma unroll 4
    for (int i = 0; i < 128; i++) s += base[(n0 + i) * INDIM];
    g_xpart[blockIdx.y * INDIM + col] = s;
}

// ---------------------------------------------------------------------------
// 3b) sumV[j] = (sum_n x[n]) . Wv[:,j] + N*bv[j]   — partial reduce fused in.
// ---------------------------------------------------------------------------
__global__ void sumv_kernel(const float* __restrict__ Wv, const float* __restrict__ bv) {
    __shared__ float xs[INDIM];
    for (int c = threadIdx.x; c < INDIM; c += 128) {
        float s = 0.f;
#pragma unroll
        for (int p = 0; p < NPARTX; p++) s += g_xpart[p * INDIM + c];
        xs[c] = s;
    }
    __syncthreads();
    const int j = blockIdx.x * 128 + threadIdx.x;       // 0..511
    float s = 0.f;
#pragma unroll 8
    for (int k = 0; k < INDIM; k++)
        s = fmaf(xs[k], Wv[k * HD + j], s);
    g_sumV[j] = s + (float)NN * bv[j];
}

// ---------------------------------------------------------------------------
// 4) head-7 projection GEMM: qkv7 = x @ [Wq|Wk|Wv][:,448:512], K split in 2.
//    grid (3, 48, 2): x=matrix sel, y=row tile, z=K half. 128 thr, 8x4 micro.
// ---------------------------------------------------------------------------
__global__ __launch_bounds__(128, 2) void proj7_kernel(
    const float* __restrict__ x,
    const float* __restrict__ Wq, const float* __restrict__ Wk, const float* __restrict__ Wv,
    const float* __restrict__ bq, const float* __restrict__ bk, const float* __restrict__ bv)
{
    __shared__ float As[2][GBK][SPAD];   // As[buf][k][m] (x transposed in tile)
    __shared__ float Bs[2][GBK][SPAD];   // Bs[buf][k][j]

    const int tid = threadIdx.x;
    const int wsel = blockIdx.x;
    const int rowBase = blockIdx.y * GTM;
    const int kBase = blockIdx.z * KHALF;
    const float* W    = (wsel == 0) ? Wq : (wsel == 1) ? Wk : Wv;
    const float* bias = (wsel == 0) ? bq : (wsel == 1) ? bk : bv;

    // A loads: row = tid&63, kseg = (tid>>6)*8
    const int ar = tid & 63;
    const int ak = (tid >> 6) << 3;
    // B loads: k rows tid>>4 and +8; 4 cols at (tid&15)*4
    const int bk0 = tid >> 4;
    const int bj  = (tid & 15) << 2;
    // compute: 8 rows x 4 cols per thread
    const int ty = tid >> 4;               // 0..7
    const int tx = tid & 15;               // 0..15

    const float* aPtr = x + (rowBase + ar) * INDIM + kBase + ak;
    const float* bPtr = W + (kBase + bk0) * HD + H7Q + bj;

    float acc[8][4];
#pragma unroll
    for (int i = 0; i < 8; i++)
#pragma unroll
        for (int j = 0; j < 4; j++) acc[i][j] = 0.f;

    // prologue -> buffer 0
    {
        float4 a0 = *(const float4*)(aPtr);
        float4 a1 = *(const float4*)(aPtr + 4);
        float4 b0 = *(const float4*)(bPtr);
        float4 b1 = *(const float4*)(bPtr + 8 * HD);
        As[0][ak + 0][ar] = a0.x; As[0][ak + 1][ar] = a0.y;
        As[0][ak + 2][ar] = a0.z; As[0][ak + 3][ar] = a0.w;
        As[0][ak + 4][ar] = a1.x; As[0][ak + 5][ar] = a1.y;
        As[0][ak + 6][ar] = a1.z; As[0][ak + 7][ar] = a1.w;
        *(float4*)(&Bs[0][bk0][bj])     = b0;
        *(float4*)(&Bs[0][bk0 + 8][bj]) = b1;
    }
    __syncthreads();

    const int NIT = KHALF / GBK;           // 16
    for (int it = 0; it < NIT; it++) {
        const int buf = it & 1;
        float4 a0, a1, b0, b1;
        if (it + 1 < NIT) {
            const float* ap = aPtr + (it + 1) * GBK;
            const float* bp = bPtr + (it + 1) * GBK * HD;
            a0 = *(const float4*)(ap);
            a1 = *(const float4*)(ap + 4);
            b0 = *(const float4*)(bp);
            b1 = *(const float4*)(bp + 8 * HD);
        }

#pragma unroll
        for (int kk = 0; kk < GBK; kk++) {
            float a[8], b[4];
            *(float4*)(a)     = *(const float4*)(&As[buf][kk][ty * 8]);
            *(float4*)(a + 4) = *(const float4*)(&As[buf][kk][ty * 8 + 4]);
            *(float4*)(b)     = *(const float4*)(&Bs[buf][kk][tx * 4]);
#pragma unroll
            for (int i = 0; i < 8; i++)
#pragma unroll
                for (int j = 0; j < 4; j++) acc[i][j] = fmaf(a[i], b[j], acc[i][j]);
        }

        if (it + 1 < NIT) {
            const int nb = buf ^ 1;
            As[nb][ak + 0][ar] = a0.x; As[nb][ak + 1][ar] = a0.y;
            As[nb][ak + 2][ar] = a0.z; As[nb][ak + 3][ar] = a0.w;
            As[nb][ak + 4][ar] = a1.x; As[nb][ak + 5][ar] = a1.y;
            As[nb][ak + 6][ar] = a1.z; As[nb][ak + 7][ar] = a1.w;
            *(float4*)(&Bs[nb][bk0][bj])     = b0;
            *(float4*)(&Bs[nb][bk0 + 8][bj]) = b1;
            __syncthreads();
        }
    }

    // epilogue: partials; bias added only in K-half 0
    float* dst = g_p7[blockIdx.z];
#pragma unroll
    for (int i = 0; i < 8; i++) {
        const int r = rowBase + ty * 8 + i;
        const int cl = tx * 4;
        float4 o;
        o.x = acc[i][0]; o.y = acc[i][1]; o.z = acc[i][2]; o.w = acc[i][3];
        if (blockIdx.z == 0) {
            o.x += bias[H7Q + cl + 0];
            o.y += bias[H7Q + cl + 1];
            o.z += bias[H7Q + cl + 2];
            o.w += bias[H7Q + cl + 3];
        }
        *(float4*)(dst + r * P7W + wsel * 64 + cl) = o;
    }
}

// 4b) combine the two K-half partials. Grid-strided second element keeps every
//     warp's float4 accesses fully coalesced on all three streams.
#define R7_TOTAL (NN * P7W / 4)            // float4 count = 147456
__global__ void reduce7_kernel() {
    int i = blockIdx.x * blockDim.x + threadIdx.x;
#pragma unroll
    for (int u = 0; u < 2; u++) {
        int idx = i + u * (R7_TOTAL / 2);
        float4 a = ((const float4*)g_p7[0])[idx];
        float4 b = ((const float4*)g_p7[1])[idx];
        float4 o;
        o.x = a.x + b.x; o.y = a.y + b.y; o.z = a.z + b.z; o.w = a.w + b.w;
        ((float4*)g_qkv7)[idx] = o;
    }
}

// ---------------------------------------------------------------------------
// 5) head 7 + fill, one block per output row.
//    Threads 0..111 write the uniform-head region [0,448) = sumV/N (float4).
//    All 4 warps run the sparse-corrected softmax for head 7:
//    out7[n,d] = (sumV7[d] + sum_{m in E(n)} (e^s - 1) v7[m,d])
//              / (N + sum (e^s - 1)),   s = q7[n].k7[m] / 8
// ---------------------------------------------------------------------------
__global__ __launch_bounds__(128) void head7_kernel(float* __restrict__ out) {
    const int n = blockIdx.x;
    const int w = threadIdx.x >> 5;
    const int lane = threadIdx.x & 31;

    __shared__ float s_acc[4][64];
    __shared__ float s_w[4];

    // fill region [0,448): 112 float4s
    if (threadIdx.x < 112) {
        const float invN = 1.0f / (float)NN;
        float4 sv = ((const float4*)g_sumV)[threadIdx.x];
        float4 o;
        o.x = sv.x * invN; o.y = sv.y * invN;
        o.z = sv.z * invN; o.w = sv.w * invN;
        ((float4*)(out + n * HD))[threadIdx.x] = o;
    }

    const float* qrow = g_qkv7 + n * P7W;               // q7
    const float qa = qrow[lane];
    const float qb = qrow[lane + 32];

    float acc0 = 0.f, acc1 = 0.f, wsum = 0.f;
    const unsigned* mrow = g_mask + n * MW;

#pragma unroll 2
    for (int word = w * 24; word < w * 24 + 24; word++) {
        unsigned bits = mrow[word];
        while (bits) {
            int b = __ffs(bits) - 1;
            bits &= bits - 1;
            int m = (word << 5) + b;
            const float* krow = g_qkv7 + m * P7W + 64;  // k7
            float p = qa * krow[lane] + qb * krow[lane + 32];
#pragma unroll
            for (int off = 16; off; off >>= 1)
                p += __shfl_xor_sync(0xffffffffu, p, off);
            float wgt = __expf(p * 0.125f) - 1.f;       // 1/sqrt(64)
            const float* vrow = g_qkv7 + m * P7W + 128; // v7
            acc0 += wgt * vrow[lane];
            acc1 += wgt * vrow[lane + 32];
            wsum += wgt;
        }
    }
    s_acc[w][lane]      = acc0;
    s_acc[w][lane + 32] = acc1;
    if (lane == 0) s_w[w] = wsum;
    __syncthreads();

    int d = threadIdx.x;
    if (d < 64) {
        float a = s_acc[0][d] + s_acc[1][d] + s_acc[2][d] + s_acc[3][d];
        float W = s_w[0] + s_w[1] + s_w[2] + s_w[3];
        out[n * HD + H7Q + d] = (g_sumV[H7Q + d] + a) / ((float)NN + W);
    }
}

// ---------------------------------------------------------------------------
extern "C" void kernel_launch(void* const* d_in, const int* in_sizes, int n_in,
                              void* d_out, int out_size) {
    const float* x  = (const float*)d_in[0];
    const void*  ei = d_in[1];
    const float* Wq = (const float*)d_in[2];
    const float* Wk = (const float*)d_in[3];
    const float* Wv = (const float*)d_in[4];
    const float* bq = (const float*)d_in[5];
    const float* bk = (const float*)d_in[6];
    const float* bv = (const float*)d_in[7];
    float* out = (float*)d_out;

    const int E = in_sizes[1] / 2;

    zero_mask_kernel<<<576, 256>>>();
    int nscan = E < 2048 ? E : 2048;
    detect_kernel<<<1, 256>>>((const int*)ei, nscan);
    build_mask_kernel<<<(E + 255) / 256, 256>>>(ei, E);

    xsum_partial_kernel<<<dim3(INDIM / 128, NPARTX), 128>>>(x);
    sumv_kernel<<<HD / 128, 128>>>(Wv, bv);

    proj7_kernel<<<dim3(3, NN / GTM, 2), 128>>>(x, Wq, Wk, Wv, bq, bk, bv);
    reduce7_kernel<<<(R7_TOTAL / 2) / 256, 256>>>();

    head7_kernel<<<NN, 128>>>(out);
}